// round 4
// baseline (speedup 1.0000x reference)
#include <cuda_runtime.h>

#define GRID 128
#define NTHR 256
#define Bsz 64
#define Ssz 1024
#define Tsz 300
#define Hsz 512
#define Vsz 5000
#define KQn 256
#define KC  128
#define AP  133

// ---------------- device scratch (static, allocation-free) ----------------
__device__ float g_k[Bsz * Ssz * KQn];        // projected keys
__device__ float g_v[Bsz * Ssz * Hsz];        // projected values
__device__ float g_h1[2][Bsz * Hsz];
__device__ float g_c1[Bsz * Hsz];
__device__ float g_h2[2][Bsz * Hsz];
__device__ float g_c2[Bsz * Hsz];
__device__ float g_ctx[Bsz * Hsz];
__device__ float g_cdnp[4][Bsz * Hsz];        // cdn split-K partials
__device__ unsigned g_count;                   // barrier arrival counter
__device__ unsigned g_gen;                     // barrier generation

// ---------------- grid-wide barrier (generation counter) ----------------
__device__ __forceinline__ void gsync() {
    __syncthreads();
    if (threadIdx.x == 0) {
        __threadfence();
        volatile unsigned* genp = &g_gen;
        unsigned old = *genp;
        if (atomicAdd(&g_count, 1u) == gridDim.x - 1u) {
            atomicExch(&g_count, 0u);
            __threadfence();
            atomicAdd(&g_gen, 1u);
        } else {
            while (*genp == old) __nanosleep(64);
        }
        __threadfence();
    }
    __syncthreads();
}

__device__ __forceinline__ float sigf(float x) { return 1.f / (1.f + __expf(-x)); }

// ---------------- 64(M) x 16(N) GEMM chunk, K streamed in 128 slices -------
// out[b][c] = sum_k A[b][k] * B[n(c)][k], result staged to gout[64][17].
// MODE 0: kv-proj   A = A0 + b*512 (pre-offset enc rows), B width 512
// MODE 1: gates1    A = [emb[tok[b]] | ctx | h1old], B = [Wih1(1024) | Whh1(512)]
//                   col map n(c) = (c>>2)*512 + u0 + (c&3)
// MODE 2: gates2    A = [h1new | h2old], B = [Wih2(512) | Whh2(512)], same col map
// MODE 3: cdn       A = [h2new | ctx], B = Wcdn (width 1024), k range = quarter
// MODE 4: logits    A[b][k] = relu(bcdn[k] + sum_z cdnp[z][b][k]), B = emb (512)
template <int MODE>
__device__ __forceinline__ void gemm_chunk(
    int u0, int nbase, int Ntot, int kbeg, int kend,
    const float* __restrict__ A0, const float* __restrict__ A1,
    const float* __restrict__ A2,
    const float* __restrict__ B0, const float* __restrict__ B1,
    float (&As)[64][AP], float (&Bst)[KC][18], float (&gout)[64][17],
    const int* __restrict__ toks)
{
    const int tid = threadIdx.x;
    const int b2 = tid & 31, c2 = tid >> 5;
    float a00 = 0.f, a01 = 0.f, a10 = 0.f, a11 = 0.f;

    for (int k0 = kbeg; k0 < kend; k0 += KC) {
        // ---- A tile fill: 64 rows x 128 k, row-major, conflict-free STS ----
        {
            const int bb = tid & 63, kq = tid >> 6;   // kq 0..3
            if (MODE == 4) {
                const float* p = A0 + bb * 512 + k0;  // cdnp[0] row
#pragma unroll
                for (int i = 0; i < 8; i++) {
                    int kk = kq * 32 + i * 4;
                    float4 v0 = *(const float4*)(p + kk);
                    float4 v1 = *(const float4*)(p + 32768 + kk);
                    float4 v2 = *(const float4*)(p + 65536 + kk);
                    float4 v3 = *(const float4*)(p + 98304 + kk);
                    float4 vb = *(const float4*)(A1 + k0 + kk);
                    As[bb][kk + 0] = fmaxf(v0.x + v1.x + v2.x + v3.x + vb.x, 0.f);
                    As[bb][kk + 1] = fmaxf(v0.y + v1.y + v2.y + v3.y + vb.y, 0.f);
                    As[bb][kk + 2] = fmaxf(v0.z + v1.z + v2.z + v3.z + vb.z, 0.f);
                    As[bb][kk + 3] = fmaxf(v0.w + v1.w + v2.w + v3.w + vb.w, 0.f);
                }
            } else {
                const float* row;
                if (MODE == 0)      row = A0 + (long)bb * 512 + k0;
                else if (MODE == 1) row = (k0 < 512)
                        ? A0 + (long)toks[bb] * 512 + k0
                        : (k0 < 1024 ? A1 + bb * 512 + (k0 - 512)
                                     : A2 + bb * 512 + (k0 - 1024));
                else                row = (k0 < 512) ? A0 + bb * 512 + k0
                                                     : A1 + bb * 512 + (k0 - 512);
#pragma unroll
                for (int i = 0; i < 8; i++) {
                    int kk = kq * 32 + i * 4;
                    float4 v = *(const float4*)(row + kk);
                    As[bb][kk + 0] = v.x; As[bb][kk + 1] = v.y;
                    As[bb][kk + 2] = v.z; As[bb][kk + 3] = v.w;
                }
            }
        }
        // ---- B tile fill: 16 cols, transposed [k][c] for broadcast reads ----
        {
            const int c = tid >> 4, kq = tid & 15;
            int n = (MODE == 1 || MODE == 2) ? (((c >> 2) << 9) + u0 + (c & 3))
                                             : nbase + c;
            bool ok = n < Ntot;
            const float* row;
            if (MODE == 1)      row = (k0 < 1024) ? B0 + (long)n * 1024 + k0
                                                  : B1 + (long)n * 512 + (k0 - 1024);
            else if (MODE == 2) row = (k0 < 512) ? B0 + (long)n * 512 + k0
                                                 : B1 + (long)n * 512 + (k0 - 512);
            else if (MODE == 3) row = B0 + (long)n * 1024 + k0;
            else                row = B0 + (long)n * 512 + k0;
#pragma unroll
            for (int i = 0; i < 2; i++) {
                int kk = kq * 8 + i * 4;
                float4 v = ok ? *(const float4*)(row + kk)
                              : make_float4(0.f, 0.f, 0.f, 0.f);
                Bst[kk + 0][c] = v.x; Bst[kk + 1][c] = v.y;
                Bst[kk + 2][c] = v.z; Bst[kk + 3][c] = v.w;
            }
        }
        __syncthreads();
#pragma unroll 8
        for (int kk = 0; kk < KC; kk++) {
            float av0 = As[2 * b2][kk];
            float av1 = As[2 * b2 + 1][kk];
            float2 bv = *(const float2*)&Bst[kk][2 * c2];
            a00 += av0 * bv.x; a01 += av0 * bv.y;
            a10 += av1 * bv.x; a11 += av1 * bv.y;
        }
        __syncthreads();
    }
    gout[2 * b2][2 * c2]     = a00; gout[2 * b2][2 * c2 + 1]     = a01;
    gout[2 * b2 + 1][2 * c2] = a10; gout[2 * b2 + 1][2 * c2 + 1] = a11;
    __syncthreads();
}

// ---------------- the persistent mega-kernel ----------------
__global__ void __launch_bounds__(NTHR, 1)
mega(const float* __restrict__ enc, const int* __restrict__ y,
     const float* __restrict__ emb,
     const float* __restrict__ Wq, const float* __restrict__ bq,
     const float* __restrict__ Wk, const float* __restrict__ bk,
     const float* __restrict__ Wv, const float* __restrict__ bv,
     const float* __restrict__ Wih1, const float* __restrict__ bih1,
     const float* __restrict__ Whh1, const float* __restrict__ bhh1,
     const float* __restrict__ Wih2, const float* __restrict__ bih2,
     const float* __restrict__ Whh2, const float* __restrict__ bhh2,
     const float* __restrict__ Wcdn, const float* __restrict__ bcdn,
     const float* __restrict__ bcls, float* __restrict__ out)
{
    __shared__ __align__(16) float As[64][AP];
    __shared__ __align__(16) float Bst[KC][18];
    __shared__ __align__(16) float gout[64][17];
    __shared__ int toks[64];

    const int tid = threadIdx.x;
    const int bx = blockIdx.x;

    // ---- phase 0: zero recurrent state + kv projection ----
    if (bx < 5) {
        float* z = bx == 0 ? g_h1[0] : bx == 1 ? g_c1 : bx == 2 ? g_h2[0]
                 : bx == 3 ? g_c2 : g_ctx;
        for (int i = tid; i < Bsz * Hsz; i += NTHR) z[i] = 0.f;
    }
    for (int cid = bx; cid < 16384 + 32768; cid += GRID) {
        if (cid < 16384) {                              // k-proj chunk
            int rt = cid >> 4, nb = (cid & 15) * 16;
            gemm_chunk<0>(0, nb, 1 << 30, 0, 512, enc + (long)rt * 64 * 512,
                          nullptr, nullptr, Wk, nullptr, As, Bst, gout, toks);
            float* dst = g_k + (long)rt * 64 * KQn;
            for (int e = tid; e < 1024; e += NTHR) {
                int b = e >> 4, c = e & 15;
                dst[(long)b * KQn + nb + c] = gout[b][c] + bk[nb + c];
            }
            __syncthreads();
        } else {                                        // v-proj chunk
            int vid = cid - 16384;
            int rt = vid >> 5, nb = (vid & 31) * 16;
            gemm_chunk<0>(0, nb, 1 << 30, 0, 512, enc + (long)rt * 64 * 512,
                          nullptr, nullptr, Wv, nullptr, As, Bst, gout, toks);
            float* dst = g_v + (long)rt * 64 * Hsz;
            for (int e = tid; e < 1024; e += NTHR) {
                int b = e >> 4, c = e & 15;
                dst[(long)b * Hsz + nb + c] = gout[b][c] + bv[nb + c];
            }
            __syncthreads();
        }
    }
    gsync();

    // ---- decoder time loop ----
    for (int t = 0; t < Tsz; t++) {
        const float* h1o = g_h1[t & 1];
        float*       h1n = g_h1[(t + 1) & 1];
        const float* h2o = g_h2[t & 1];
        float*       h2n = g_h2[(t + 1) & 1];

        // Phase 1: LSTM1 gates GEMM + fused cell (block owns units 4*bx..4*bx+3)
        {
            if (tid < 64) toks[tid] = (t == 0) ? 0 : y[tid * Tsz + (t - 1)];
            __syncthreads();
            int u0 = bx * 4;
            gemm_chunk<1>(u0, 0, 1 << 30, 0, 1536, emb, g_ctx, h1o,
                          Wih1, Whh1, As, Bst, gout, toks);
            int b = tid >> 2, du = tid & 3, u = u0 + du;
            float gi = gout[b][du]      + bih1[u]          + bhh1[u];
            float gf = gout[b][4 + du]  + bih1[512 + u]    + bhh1[512 + u];
            float gg = gout[b][8 + du]  + bih1[1024 + u]   + bhh1[1024 + u];
            float go = gout[b][12 + du] + bih1[1536 + u]   + bhh1[1536 + u];
            float cold = g_c1[b * Hsz + u];
            float cn = sigf(gf) * cold + sigf(gi) * tanhf(gg);
            g_c1[b * Hsz + u] = cn;
            h1n[b * Hsz + u] = sigf(go) * tanhf(cn);
            gsync();
        }

        // Phase 2: LSTM2 gates GEMM + fused cell
        {
            int u0 = bx * 4;
            gemm_chunk<2>(u0, 0, 1 << 30, 0, 1024, h1n, h2o, nullptr,
                          Wih2, Whh2, As, Bst, gout, toks);
            int b = tid >> 2, du = tid & 3, u = u0 + du;
            float gi = gout[b][du]      + bih2[u]          + bhh2[u];
            float gf = gout[b][4 + du]  + bih2[512 + u]    + bhh2[512 + u];
            float gg = gout[b][8 + du]  + bih2[1024 + u]   + bhh2[1024 + u];
            float go = gout[b][12 + du] + bih2[1536 + u]   + bhh2[1536 + u];
            float cold = g_c2[b * Hsz + u];
            float cn = sigf(gf) * cold + sigf(gi) * tanhf(gg);
            g_c2[b * Hsz + u] = cn;
            h2n[b * Hsz + u] = sigf(go) * tanhf(cn);
            gsync();
        }

        // Phase 3: fused attention, one block per batch element
        if (bx < Bsz) {
            float* h2s = &As[0][0];
            float* qs  = h2s + 512;
            float* sc  = qs + 256;
            float* red = sc + 1024;
            int b = bx, lane = tid & 31, w = tid >> 5;

            h2s[tid]       = h2n[b * 512 + tid];
            h2s[tid + 256] = h2n[b * 512 + 256 + tid];
            __syncthreads();

            const float4* h24 = (const float4*)h2s;
            for (int jj = 0; jj < 32; jj++) {
                int j = (w << 5) + jj;
                const float4* wr = (const float4*)(Wq + (long)j * 512);
                float s = 0.f;
#pragma unroll
                for (int it = 0; it < 4; it++) {
                    float4 hv = h24[it * 32 + lane];
                    float4 wv = wr[it * 32 + lane];
                    s += hv.x * wv.x + hv.y * wv.y + hv.z * wv.z + hv.w * wv.w;
                }
#pragma unroll
                for (int o = 16; o; o >>= 1) s += __shfl_xor_sync(0xffffffffu, s, o);
                if (lane == 0) qs[j] = (s + bq[j]) * 0.0625f;
            }
            __syncthreads();

            const float4* q4 = (const float4*)qs;
            float4 qr0 = q4[lane], qr1 = q4[32 + lane];
#pragma unroll 2
            for (int i = 0; i < 128; i++) {
                int sidx = (i << 3) + w;
                const float4* kr = (const float4*)(g_k + ((long)b * 1024 + sidx) * 256);
                float4 k0 = kr[lane], k1 = kr[32 + lane];
                float acc = qr0.x * k0.x + qr0.y * k0.y + qr0.z * k0.z + qr0.w * k0.w
                          + qr1.x * k1.x + qr1.y * k1.y + qr1.z * k1.z + qr1.w * k1.w;
#pragma unroll
                for (int o = 16; o; o >>= 1) acc += __shfl_xor_sync(0xffffffffu, acc, o);
                if (lane == 0) sc[sidx] = acc;
            }
            __syncthreads();

            float mx = -1e30f;
#pragma unroll
            for (int i = 0; i < 4; i++) mx = fmaxf(mx, sc[tid + i * 256]);
#pragma unroll
            for (int o = 16; o; o >>= 1) mx = fmaxf(mx, __shfl_xor_sync(0xffffffffu, mx, o));
            if (lane == 0) red[w] = mx;
            __syncthreads();
            mx = red[0];
#pragma unroll
            for (int i = 1; i < 8; i++) mx = fmaxf(mx, red[i]);
            __syncthreads();

            float ls = 0.f;
#pragma unroll
            for (int i = 0; i < 4; i++) {
                float e = __expf(sc[tid + i * 256] - mx);
                sc[tid + i * 256] = e;
                ls += e;
            }
#pragma unroll
            for (int o = 16; o; o >>= 1) ls += __shfl_xor_sync(0xffffffffu, ls, o);
            if (lane == 0) red[w] = ls;
            __syncthreads();
            float tot = red[0] + red[1] + red[2] + red[3]
                      + red[4] + red[5] + red[6] + red[7];
            float inv = 1.f / tot;

            float2 acc2 = make_float2(0.f, 0.f);
            const float2* vb = (const float2*)(g_v + (long)b * 1024 * 512);
#pragma unroll 4
            for (int s2 = 0; s2 < 1024; s2++) {
                float wsc = sc[s2];
                float2 vv = vb[(long)s2 * 256 + tid];
                acc2.x += wsc * vv.x;
                acc2.y += wsc * vv.y;
            }
            g_ctx[b * 512 + 2 * tid]     = acc2.x * inv;
            g_ctx[b * 512 + 2 * tid + 1] = acc2.y * inv;
        }
        gsync();

        // Phase 4: cdn partial GEMM (32 col-chunks x 4-way split-K)
        {
            int nb = (bx >> 2) * 16;
            int kq = bx & 3;
            gemm_chunk<3>(0, nb, 1 << 30, kq * 256, kq * 256 + 256, h2n, g_ctx,
                          nullptr, Wcdn, nullptr, As, Bst, gout, toks);
            float* dst = g_cdnp[kq];
            for (int e = tid; e < 1024; e += NTHR) {
                int b = e >> 4, c = e & 15;
                dst[b * Hsz + nb + c] = gout[b][c];
            }
            gsync();
        }

        // Phase 5: logits GEMM (cdn finish fused into A load), 313 chunks
        {
            for (int ci = bx; ci < 313; ci += GRID) {
                int nb = ci * 16;
                gemm_chunk<4>(0, nb, Vsz, 0, 512, g_cdnp[0], bcdn, nullptr,
                              emb, nullptr, As, Bst, gout, toks);
                for (int e = tid; e < 1024; e += NTHR) {
                    int b = e >> 4, c = e & 15;
                    int n = nb + c;
                    if (n < Vsz)
                        out[((long)b * Tsz + t) * Vsz + n] = gout[b][c] + bcls[n];
                }
                __syncthreads();
            }
            gsync();
        }
    }
}

// ---------------- host launch: ONE kernel, ONE graph node ----------------
extern "C" void kernel_launch(void* const* d_in, const int* in_sizes, int n_in,
                              void* d_out, int out_size) {
    mega<<<GRID, NTHR>>>(
        (const float*)d_in[0],  (const int*)d_in[1],   (const float*)d_in[2],
        (const float*)d_in[3],  (const float*)d_in[4],
        (const float*)d_in[5],  (const float*)d_in[6],
        (const float*)d_in[7],  (const float*)d_in[8],
        (const float*)d_in[9],  (const float*)d_in[10],
        (const float*)d_in[11], (const float*)d_in[12],
        (const float*)d_in[13], (const float*)d_in[14],
        (const float*)d_in[15], (const float*)d_in[16],
        (const float*)d_in[17], (const float*)d_in[18],
        (const float*)d_in[19], (float*)d_out);
}

// round 5
// speedup vs baseline: 2.2417x; 2.2417x over previous
#include <cuda_runtime.h>

#define GRID 128
#define NTHR 256
#define Bsz 64
#define Ssz 1024
#define Tsz 300
#define Hsz 512
#define Vsz 5000
#define KQn 256

typedef unsigned long long ull;

// ---------------- device scratch ----------------
__device__ float g_k[Bsz * Ssz * KQn];
__device__ float g_v[Bsz * Ssz * Hsz];
__device__ float g_h1[2][Bsz * Hsz];
__device__ float g_c1[Bsz * Hsz];
__device__ float g_h2[2][Bsz * Hsz];
__device__ float g_c2[Bsz * Hsz];
__device__ float g_ctx[Bsz * Hsz];
__device__ float g_cdn[Bsz * Hsz];
__device__ float g_sc[Bsz * 1024];
__device__ float g_g1p[4 * Bsz * 2048];
__device__ float g_g2p[8 * Bsz * 2048];
__device__ float g_cdp[32 * Bsz * 512];
__device__ volatile int g_flags[GRID];
__device__ volatile int g_genv;

// ---------------- shared arena ----------------
struct Sh {
    union {
        struct { float As[64][34]; float Bs[128][34]; } g;
        struct { float h2s[512]; float qs[256]; float sc[1024]; float red[8]; } a;
    } u;
    int toks[64];
};

// ---------------- grid barrier: flags + single release word ----------------
__device__ __forceinline__ void gsync(int& gs) {
    gs++;
    __syncthreads();
    if (blockIdx.x == 0) {
        if (threadIdx.x > 0 && threadIdx.x < GRID)
            while (g_flags[threadIdx.x] < gs) __nanosleep(32);
        __syncthreads();
        if (threadIdx.x == 0) { __threadfence(); g_genv = gs; }
    } else if (threadIdx.x == 0) {
        __threadfence();
        g_flags[blockIdx.x] = gs;
        while (g_genv < gs) __nanosleep(32);
    }
    __syncthreads();
    __threadfence();
}

__device__ __forceinline__ float sigf(float x) { return 1.f / (1.f + __expf(-x)); }

__device__ __forceinline__ void fma2(ull& d, ull a, ull b) {
    asm("fma.rn.f32x2 %0, %1, %2, %3;" : "=l"(d) : "l"(a), "l"(b), "l"(d));
}
__device__ __forceinline__ float pairsum(ull x) {
    float lo, hi;
    asm("mov.b64 {%0, %1}, %2;" : "=f"(lo), "=f"(hi) : "l"(x));
    return lo + hi;
}

// ---------------- 64(M) x 128(N) GEMM tile, f32x2 k-paired ----------------
// out[m][nbase+n] = sum_{k in [kbeg,kend)} A[m][k] * B[n][k]
// AM 0: A row-major, stride arow.  AM 1: [emb[tok[m]]|A1|A2] each 512.
// AM 2: [A0 (512) | A1 (512)].
// B row n: k<segB -> B0 (row len L0) else B1 (row len L1, k-segB).
template <int AM>
__device__ __forceinline__ void gemm2(
    const float* __restrict__ A0, const float* __restrict__ A1,
    const float* __restrict__ A2, long arow,
    const float* __restrict__ B0, long L0, int segB,
    const float* __restrict__ B1, long L1,
    int nbase, int Nmax, int kbeg, int kend,
    float* __restrict__ outp, long OS, const float* __restrict__ bias,
    const int* __restrict__ yy, int t, Sh& sh)
{
    const int tid = threadIdx.x;
    const int nt = tid & 31;        // lane
    const int mt = tid >> 5;        // warp (uniform)

    if (AM == 1) {
        if (tid < 64) sh.toks[tid] = (t == 0) ? 0 : yy[tid * Tsz + (t - 1)];
        __syncthreads();
    }

    ull acc[8][4];
#pragma unroll
    for (int i = 0; i < 8; i++)
#pragma unroll
        for (int j = 0; j < 4; j++) acc[i][j] = 0ULL;

    for (int kb = kbeg; kb < kend; kb += 32) {
        // A fill: 64 x 32
        {
            const int m = tid >> 2, kq = tid & 3;
#pragma unroll
            for (int p = 0; p < 2; p++) {
                int k4 = (kq * 2 + p) * 4;
                int k = kb + k4;
                const float* rp;
                if (AM == 0)      rp = A0 + (long)m * arow + k;
                else if (AM == 1) rp = (k < 512)  ? A0 + (long)sh.toks[m] * 512 + k
                                 : (k < 1024) ? A1 + m * 512 + (k - 512)
                                              : A2 + m * 512 + (k - 1024);
                else              rp = (k < 512) ? A0 + m * 512 + k
                                                 : A1 + m * 512 + (k - 512);
                float4 v = *(const float4*)rp;
                float* d = &sh.u.g.As[m][k4];
                ((float2*)d)[0] = make_float2(v.x, v.y);
                ((float2*)d)[1] = make_float2(v.z, v.w);
            }
            // B fill: 128 x 32
            const int kq8 = tid & 7;
#pragma unroll
            for (int p = 0; p < 4; p++) {
                int n = (tid >> 3) + 32 * p;
                int k4 = kq8 * 4;
                int k = kb + k4;
                int ng = nbase + n;
                float4 v = make_float4(0.f, 0.f, 0.f, 0.f);
                if (ng < Nmax) {
                    const float* rp = (k < segB) ? B0 + (long)ng * L0 + k
                                                 : B1 + (long)ng * L1 + (k - segB);
                    v = *(const float4*)rp;
                }
                float* d = &sh.u.g.Bs[n][k4];
                ((float2*)d)[0] = make_float2(v.x, v.y);
                ((float2*)d)[1] = make_float2(v.z, v.w);
            }
        }
        __syncthreads();
#pragma unroll 2
        for (int kk = 0; kk < 16; kk++) {
            ull a[8], b[4];
#pragma unroll
            for (int j = 0; j < 4; j++)
                b[j] = *(const ull*)&sh.u.g.Bs[nt + 32 * j][2 * kk];
#pragma unroll
            for (int i = 0; i < 8; i++)
                a[i] = *(const ull*)&sh.u.g.As[mt * 8 + i][2 * kk];
#pragma unroll
            for (int i = 0; i < 8; i++)
#pragma unroll
                for (int j = 0; j < 4; j++) fma2(acc[i][j], a[i], b[j]);
        }
        __syncthreads();
    }

#pragma unroll
    for (int i = 0; i < 8; i++) {
        long m = mt * 8 + i;
#pragma unroll
        for (int j = 0; j < 4; j++) {
            int n = nbase + nt + 32 * j;
            if (n < Nmax) {
                float s = pairsum(acc[i][j]);
                if (bias) s += bias[n];
                outp[m * OS + n] = s;
            }
        }
    }
    __syncthreads();
}

// ---------------- persistent mega-kernel ----------------
__global__ void __launch_bounds__(NTHR, 1)
mega(const float* __restrict__ enc, const int* __restrict__ y,
     const float* __restrict__ emb,
     const float* __restrict__ Wq, const float* __restrict__ bq,
     const float* __restrict__ Wk, const float* __restrict__ bk,
     const float* __restrict__ Wv, const float* __restrict__ bv,
     const float* __restrict__ Wih1, const float* __restrict__ bih1,
     const float* __restrict__ Whh1, const float* __restrict__ bhh1,
     const float* __restrict__ Wih2, const float* __restrict__ bih2,
     const float* __restrict__ Whh2, const float* __restrict__ bhh2,
     const float* __restrict__ Wcdn, const float* __restrict__ bcdn,
     const float* __restrict__ bcls, float* __restrict__ out)
{
    __shared__ Sh sh;
    const int tid = threadIdx.x;
    const int bx = blockIdx.x;
    int gs = g_genv;

    // ---- init: zero state ----
    for (int i = bx * NTHR + tid; i < 5 * Bsz * Hsz; i += GRID * NTHR) {
        int a = i >> 15, j = i & 32767;
        float* p = a == 0 ? g_h1[0] : a == 1 ? g_c1 : a == 2 ? g_h2[0]
                 : a == 3 ? g_c2 : g_ctx;
        p[j] = 0.f;
    }
    // ---- kv projection: 1024 m-tiles x (2 K-tiles + 4 V-tiles) ----
    for (int j = bx; j < 1024 * 6; j += GRID) {
        if (j < 2048) {
            int mt_ = j >> 1, nt_ = j & 1;
            gemm2<0>(enc + (long)mt_ * 64 * 512, nullptr, nullptr, 512,
                     Wk, 512, 1 << 30, nullptr, 0,
                     nt_ * 128, 1 << 30, 0, 512,
                     g_k + (long)mt_ * 64 * KQn, KQn, bk, nullptr, 0, sh);
        } else {
            int v = j - 2048;
            int mt_ = v >> 2, nt_ = v & 3;
            gemm2<0>(enc + (long)mt_ * 64 * 512, nullptr, nullptr, 512,
                     Wv, 512, 1 << 30, nullptr, 0,
                     nt_ * 128, 1 << 30, 0, 512,
                     g_v + (long)mt_ * 64 * Hsz, Hsz, bv, nullptr, 0, sh);
        }
    }
    gsync(gs);

    // ---- decoder loop; logits(t-1) overlapped into phase A of step t ----
    for (int t = 0; t < Tsz; t++) {
        const float* h1o = g_h1[t & 1];
        float*       h1n = g_h1[(t + 1) & 1];
        const float* h2o = g_h2[t & 1];
        float*       h2n = g_h2[(t + 1) & 1];

        // Phase A: logits(t-1) [40 units] || LSTM1 gates(t) [64 units, splitK 4]
        {
            int lbase = (t > 0) ? 40 : 0;
            if (t > 0 && bx < 40) {
                gemm2<0>(g_cdn, nullptr, nullptr, 512,
                         emb, 512, 1 << 30, nullptr, 0,
                         bx * 128, Vsz, 0, 512,
                         out + (long)(t - 1) * Vsz, (long)Tsz * Vsz, bcls,
                         nullptr, 0, sh);
            } else if (bx >= lbase && bx < lbase + 64) {
                int u = bx - lbase, ntile = u >> 2, ks = u & 3;
                gemm2<1>(emb, g_ctx, h1o, 0,
                         Wih1, 1024, 1024, Whh1, 512,
                         ntile * 128, 1 << 30, ks * 384, ks * 384 + 384,
                         g_g1p + (long)ks * (Bsz * 2048), 2048, nullptr, y, t, sh);
            }
            gsync(gs);
        }
        // Phase B: LSTM1 cell
        {
            int idx = bx * NTHR + tid, b = idx >> 9, u = idx & 511;
            float gt[4];
#pragma unroll
            for (int g = 0; g < 4; g++) {
                int n = g * 512 + u;
                float s = bih1[n] + bhh1[n];
#pragma unroll
                for (int ks = 0; ks < 4; ks++) s += g_g1p[ks * 131072 + b * 2048 + n];
                gt[g] = s;
            }
            float cn = sigf(gt[1]) * g_c1[idx] + sigf(gt[0]) * tanhf(gt[2]);
            g_c1[idx] = cn;
            h1n[idx] = sigf(gt[3]) * tanhf(cn);
            gsync(gs);
        }
        // Phase C: LSTM2 gates [128 units, splitK 8]
        {
            int ntile = bx >> 3, ks = bx & 7;
            gemm2<2>(h1n, h2o, nullptr, 0,
                     Wih2, 512, 512, Whh2, 512,
                     ntile * 128, 1 << 30, ks * 128, ks * 128 + 128,
                     g_g2p + (long)ks * (Bsz * 2048), 2048, nullptr, nullptr, 0, sh);
            gsync(gs);
        }
        // Phase D: LSTM2 cell
        {
            int idx = bx * NTHR + tid, b = idx >> 9, u = idx & 511;
            float gt[4];
#pragma unroll
            for (int g = 0; g < 4; g++) {
                int n = g * 512 + u;
                float s = bih2[n] + bhh2[n];
#pragma unroll
                for (int ks = 0; ks < 8; ks++) s += g_g2p[ks * 131072 + b * 2048 + n];
                gt[g] = s;
            }
            float cn = sigf(gt[1]) * g_c2[idx] + sigf(gt[0]) * tanhf(gt[2]);
            g_c2[idx] = cn;
            h2n[idx] = sigf(gt[3]) * tanhf(cn);
            gsync(gs);
        }
        // Phase E: q-proj + half-S scores per block (2 blocks per batch)
        {
            int b = bx >> 1, half = bx & 1, lane = tid & 31, w = tid >> 5;
            sh.u.a.h2s[tid]       = h2n[b * 512 + tid];
            sh.u.a.h2s[tid + 256] = h2n[b * 512 + 256 + tid];
            __syncthreads();
            const float4* h24 = (const float4*)sh.u.a.h2s;
#pragma unroll 4
            for (int jj = 0; jj < 32; jj++) {
                int j = (w << 5) + jj;
                const float4* wr = (const float4*)(Wq + (long)j * 512);
                float s = 0.f;
#pragma unroll
                for (int it = 0; it < 4; it++) {
                    float4 hv = h24[it * 32 + lane];
                    float4 wv = wr[it * 32 + lane];
                    s += hv.x * wv.x + hv.y * wv.y + hv.z * wv.z + hv.w * wv.w;
                }
#pragma unroll
                for (int o = 16; o; o >>= 1) s += __shfl_xor_sync(~0u, s, o);
                if (lane == 0) sh.u.a.qs[j] = (s + bq[j]) * 0.0625f;
            }
            __syncthreads();
            const float4* q4 = (const float4*)sh.u.a.qs;
            float4 qr0 = q4[lane], qr1 = q4[32 + lane];
            int s0 = half * 512;
#pragma unroll 2
            for (int i = 0; i < 64; i++) {
                int sidx = s0 + (i << 3) + w;
                const float4* kr = (const float4*)(g_k + ((long)b * 1024 + sidx) * 256);
                float4 k0 = kr[lane], k1 = kr[32 + lane];
                float a = qr0.x * k0.x + qr0.y * k0.y + qr0.z * k0.z + qr0.w * k0.w
                        + qr1.x * k1.x + qr1.y * k1.y + qr1.z * k1.z + qr1.w * k1.w;
#pragma unroll
                for (int o = 16; o; o >>= 1) a += __shfl_xor_sync(~0u, a, o);
                if (lane == 0) g_sc[b * 1024 + sidx] = a;
            }
            gsync(gs);
        }
        // Phase F: softmax (redundant per sibling) + half-column context
        {
            int b = bx >> 1, half = bx & 1, lane = tid & 31, w = tid >> 5;
            float* sc = sh.u.a.sc;
            float* red = sh.u.a.red;
#pragma unroll
            for (int i = 0; i < 4; i++) sc[tid + i * 256] = g_sc[b * 1024 + tid + i * 256];
            __syncthreads();
            float mx = -1e30f;
#pragma unroll
            for (int i = 0; i < 4; i++) mx = fmaxf(mx, sc[tid + i * 256]);
#pragma unroll
            for (int o = 16; o; o >>= 1) mx = fmaxf(mx, __shfl_xor_sync(~0u, mx, o));
            if (lane == 0) red[w] = mx;
            __syncthreads();
            mx = fmaxf(fmaxf(fmaxf(red[0], red[1]), fmaxf(red[2], red[3])),
                       fmaxf(fmaxf(red[4], red[5]), fmaxf(red[6], red[7])));
            __syncthreads();
            float ls = 0.f;
#pragma unroll
            for (int i = 0; i < 4; i++) {
                float e = __expf(sc[tid + i * 256] - mx);
                sc[tid + i * 256] = e;
                ls += e;
            }
#pragma unroll
            for (int o = 16; o; o >>= 1) ls += __shfl_xor_sync(~0u, ls, o);
            if (lane == 0) red[w] = ls;
            __syncthreads();
            float inv = 1.f / (red[0] + red[1] + red[2] + red[3]
                             + red[4] + red[5] + red[6] + red[7]);
            int col = half * 256 + tid;
            const float* vp = g_v + (long)b * 524288 + col;
            float a0 = 0.f, a1 = 0.f, a2 = 0.f, a3 = 0.f;
#pragma unroll 4
            for (int s2 = 0; s2 < 1024; s2 += 4) {
                a0 += sc[s2]     * vp[(long)s2 * 512];
                a1 += sc[s2 + 1] * vp[(long)(s2 + 1) * 512];
                a2 += sc[s2 + 2] * vp[(long)(s2 + 2) * 512];
                a3 += sc[s2 + 3] * vp[(long)(s2 + 3) * 512];
            }
            g_ctx[b * 512 + col] = (a0 + a1 + a2 + a3) * inv;
            gsync(gs);
        }
        // Phase G: cdn gemm [4 n-tiles x splitK 32]
        {
            int ntile = bx >> 5, ks = bx & 31;
            gemm2<2>(h2n, g_ctx, nullptr, 0,
                     Wcdn, 1024, 1 << 30, nullptr, 0,
                     ntile * 128, 1 << 30, ks * 32, ks * 32 + 32,
                     g_cdp + (long)ks * (Bsz * 512), 512, nullptr, nullptr, 0, sh);
            gsync(gs);
        }
        // Phase H: cdn reduce + bias + relu
        {
            int idx = bx * NTHR + tid;
            float s = bcdn[idx & 511];
#pragma unroll
            for (int ks = 0; ks < 32; ks++) s += g_cdp[ks * 32768 + idx];
            g_cdn[idx] = fmaxf(s, 0.f);
            gsync(gs);
        }
    }
    // final logits for t = Tsz-1
    if (bx < 40) {
        gemm2<0>(g_cdn, nullptr, nullptr, 512,
                 emb, 512, 1 << 30, nullptr, 0,
                 bx * 128, Vsz, 0, 512,
                 out + (long)(Tsz - 1) * Vsz, (long)Tsz * Vsz, bcls,
                 nullptr, 0, sh);
    }
}

extern "C" void kernel_launch(void* const* d_in, const int* in_sizes, int n_in,
                              void* d_out, int out_size) {
    mega<<<GRID, NTHR>>>(
        (const float*)d_in[0],  (const int*)d_in[1],   (const float*)d_in[2],
        (const float*)d_in[3],  (const float*)d_in[4],
        (const float*)d_in[5],  (const float*)d_in[6],
        (const float*)d_in[7],  (const float*)d_in[8],
        (const float*)d_in[9],  (const float*)d_in[10],
        (const float*)d_in[11], (const float*)d_in[12],
        (const float*)d_in[13], (const float*)d_in[14],
        (const float*)d_in[15], (const float*)d_in[16],
        (const float*)d_in[17], (const float*)d_in[18],
        (const float*)d_in[19], (float*)d_out);
}

// round 6
// speedup vs baseline: 3.1406x; 1.4010x over previous
#include <cuda_runtime.h>

#define GRID 128
#define NTHR 512
#define Bsz 64
#define Ssz 1024
#define Tsz 300
#define Hsz 512
#define Vsz 5000
#define KQn 256

typedef unsigned long long ull;

// ---------------- device scratch ----------------
__device__ float g_k[Bsz * Ssz * KQn];
__device__ float g_v[Bsz * Ssz * Hsz];
__device__ float g_h1[2][Bsz * Hsz];
__device__ float g_c1[Bsz * Hsz];
__device__ float g_h2[2][Bsz * Hsz];
__device__ float g_c2[Bsz * Hsz];
__device__ float g_ctx[Bsz * Hsz];
__device__ float g_cdn[Bsz * Hsz];
__device__ float g_g1p[8 * Bsz * 2048];
__device__ float g_g2p[8 * Bsz * 2048];
__device__ float g_cdp[32 * Bsz * 512];
__device__ float g_lgp[2][Bsz * 3072];
__device__ volatile int g_flags[GRID];
__device__ volatile int g_genv;

// ---------------- shared arena ----------------
struct __align__(16) Sh {
    union {
        struct { float As[64][36]; float Bs[128][36]; } g;
        struct { float h2s[512]; float qs[256]; float sc[1024]; float red[16]; } a;
    } u;
    int toks[64];
};

// ---------------- grid barrier ----------------
__device__ __forceinline__ void gsync(int& gs) {
    gs++;
    __syncthreads();
    if (blockIdx.x == 0) {
        if (threadIdx.x > 0 && threadIdx.x < GRID)
            while (g_flags[threadIdx.x] < gs) __nanosleep(32);
        __syncthreads();
        if (threadIdx.x == 0) { __threadfence(); g_genv = gs; }
    } else if (threadIdx.x == 0) {
        __threadfence();
        g_flags[blockIdx.x] = gs;
        while (g_genv < gs) __nanosleep(32);
    }
    __syncthreads();
    __threadfence();
}

__device__ __forceinline__ float sigf(float x) { return 1.f / (1.f + __expf(-x)); }

__device__ __forceinline__ void fma2(ull& d, ull a, ull b) {
    asm("fma.rn.f32x2 %0, %1, %2, %3;" : "=l"(d) : "l"(a), "l"(b), "l"(d));
}
__device__ __forceinline__ float pairsum(ull x) {
    float lo, hi;
    asm("mov.b64 {%0, %1}, %2;" : "=f"(lo), "=f"(hi) : "l"(x));
    return lo + hi;
}

// ---------------- 64M x 128N GEMM tile, LDS.128 f32x2 inner loop -----------
// out[m][n] = sum_k A[m][k] * B[n][k]
// AM 0: A row-major stride arow. AM 1: [emb[tok]|A1|A2] each 512.
// AM 2: [A0(512)|A1(512+)]. B: row n uses B0 (len L0) for k<segB else B1.
template <int AM>
__device__ __forceinline__ void gemm2(
    const float* __restrict__ A0, const float* __restrict__ A1,
    const float* __restrict__ A2, long arow,
    const float* __restrict__ B0, long L0, int segB,
    const float* __restrict__ B1, long L1,
    int nbase, int Nmax, int kbeg, int kend,
    float* __restrict__ outp, long OS, const float* __restrict__ bias,
    const int* __restrict__ yy, int t, Sh& sh)
{
    const int tid = threadIdx.x;
    const int nt = tid & 31;
    const int mt = tid >> 5;                 // 0..15 (warp-uniform)
    const int ar = tid >> 3;                 // 0..63
    const int kq4 = (tid & 7) * 4;           // 0..28

    if (AM == 1) {
        if (tid < 64) sh.toks[tid] = (t == 0) ? 0 : yy[tid * Tsz + (t - 1)];
        __syncthreads();
    }

    ull acc[4][4];
#pragma unroll
    for (int i = 0; i < 4; i++)
#pragma unroll
        for (int j = 0; j < 4; j++) acc[i][j] = 0ULL;

    for (int kb = kbeg; kb < kend; kb += 32) {
        // ---- A fill: 64 x 32, one float4/thread ----
        {
            int k = kb + kq4;
            const float* rp;
            if (AM == 0)      rp = A0 + (long)ar * arow + k;
            else if (AM == 1) rp = (k < 512)  ? A0 + (long)sh.toks[ar] * 512 + k
                             : (k < 1024) ? A1 + ar * 512 + (k - 512)
                                          : A2 + ar * 512 + (k - 1024);
            else              rp = (k < 512) ? A0 + ar * 512 + k
                                             : A1 + ar * 512 + (k - 512);
            *(float4*)&sh.u.g.As[ar][kq4] = *(const float4*)rp;
        }
        // ---- B fill: 128 x 32, two float4/thread ----
#pragma unroll
        for (int p = 0; p < 2; p++) {
            int n = ar + 64 * p;
            int ng = nbase + n;
            int k = kb + kq4;
            float4 v = make_float4(0.f, 0.f, 0.f, 0.f);
            if (ng < Nmax) {
                const float* rp = (k < segB) ? B0 + (long)ng * L0 + k
                                             : B1 + (long)ng * L1 + (k - segB);
                v = *(const float4*)rp;
            }
            *(float4*)&sh.u.g.Bs[n][kq4] = v;
        }
        __syncthreads();
#pragma unroll
        for (int kq = 0; kq < 8; kq++) {
            ull a0[4], a1[4], b0[4], b1[4];
#pragma unroll
            for (int j = 0; j < 4; j++) {
                ulonglong2 tb = *(const ulonglong2*)&sh.u.g.Bs[nt + 32 * j][4 * kq];
                b0[j] = tb.x; b1[j] = tb.y;
            }
#pragma unroll
            for (int i = 0; i < 4; i++) {
                ulonglong2 ta = *(const ulonglong2*)&sh.u.g.As[mt * 4 + i][4 * kq];
                a0[i] = ta.x; a1[i] = ta.y;
            }
#pragma unroll
            for (int i = 0; i < 4; i++)
#pragma unroll
                for (int j = 0; j < 4; j++) {
                    fma2(acc[i][j], a0[i], b0[j]);
                    fma2(acc[i][j], a1[i], b1[j]);
                }
        }
        __syncthreads();
    }

#pragma unroll
    for (int i = 0; i < 4; i++) {
        long m = mt * 4 + i;
#pragma unroll
        for (int j = 0; j < 4; j++) {
            int n = nbase + nt + 32 * j;
            if (n < Nmax) {
                float s = pairsum(acc[i][j]);
                if (bias) s += bias[n];
                outp[m * OS + n] = s;
            }
        }
    }
    __syncthreads();
}

// ---------------- persistent mega-kernel ----------------
__global__ void __launch_bounds__(NTHR, 1)
mega(const float* __restrict__ enc, const int* __restrict__ y,
     const float* __restrict__ emb,
     const float* __restrict__ Wq, const float* __restrict__ bq,
     const float* __restrict__ Wk, const float* __restrict__ bk,
     const float* __restrict__ Wv, const float* __restrict__ bv,
     const float* __restrict__ Wih1, const float* __restrict__ bih1,
     const float* __restrict__ Whh1, const float* __restrict__ bhh1,
     const float* __restrict__ Wih2, const float* __restrict__ bih2,
     const float* __restrict__ Whh2, const float* __restrict__ bhh2,
     const float* __restrict__ Wcdn, const float* __restrict__ bcdn,
     const float* __restrict__ bcls, float* __restrict__ out)
{
    __shared__ Sh sh;
    const int tid = threadIdx.x;
    const int bx = blockIdx.x;
    int gs = g_genv;

    // ---- init: zero recurrent state ----
    for (int i = bx * NTHR + tid; i < 5 * Bsz * Hsz; i += GRID * NTHR) {
        int a = i >> 15, j = i & 32767;
        float* p = a == 0 ? g_h1[0] : a == 1 ? g_c1 : a == 2 ? g_h2[0]
                 : a == 3 ? g_c2 : g_ctx;
        p[j] = 0.f;
    }
    // ---- kv projection ----
    for (int j = bx; j < 6144; j += GRID) {
        if (j < 2048) {
            int mt_ = j >> 1, nt_ = j & 1;
            gemm2<0>(enc + (long)mt_ * 64 * 512, nullptr, nullptr, 512,
                     Wk, 512, 1 << 30, nullptr, 0,
                     nt_ * 128, 1 << 30, 0, 512,
                     g_k + (long)mt_ * 64 * KQn, KQn, bk, nullptr, 0, sh);
        } else {
            int v = j - 2048;
            int mt_ = v >> 2, nt_ = v & 3;
            gemm2<0>(enc + (long)mt_ * 64 * 512, nullptr, nullptr, 512,
                     Wv, 512, 1 << 30, nullptr, 0,
                     nt_ * 128, 1 << 30, 0, 512,
                     g_v + (long)mt_ * 64 * Hsz, Hsz, bv, nullptr, 0, sh);
        }
    }
    gsync(gs);

    for (int t = 0; t < Tsz; t++) {
        const float* h1o = g_h1[t & 1];
        float*       h1n = g_h1[(t + 1) & 1];
        const float* h2o = g_h2[t & 1];
        float*       h2n = g_h2[(t + 1) & 1];

        // ---- P1: LSTM1 gates (16 n-tiles x splitK8, kchunk 192) ----
        {
            int ntile = bx >> 3, ks = bx & 7;
            gemm2<1>(emb, g_ctx, h1o, 0,
                     Wih1, 1024, 1024, Whh1, 512,
                     ntile * 128, 1 << 30, ks * 192, ks * 192 + 192,
                     g_g1p + (long)ks * 131072, 2048, nullptr, y, t, sh);
            gsync(gs);
        }
        // ---- P2: cell1 ----
        {
            int gid = bx * NTHR + tid;
            if (gid < 32768) {
                int b = gid >> 9, u = gid & 511;
                float gt[4];
#pragma unroll
                for (int g = 0; g < 4; g++) {
                    int n = g * 512 + u;
                    float s = bih1[n] + bhh1[n];
#pragma unroll
                    for (int ks = 0; ks < 8; ks++)
                        s += g_g1p[ks * 131072 + b * 2048 + n];
                    gt[g] = s;
                }
                float cn = sigf(gt[1]) * g_c1[gid] + sigf(gt[0]) * tanhf(gt[2]);
                g_c1[gid] = cn;
                h1n[gid] = sigf(gt[3]) * tanhf(cn);
            }
            gsync(gs);
        }
        // ---- P3: LSTM2 gates (16 n-tiles x splitK8, kchunk 128) ----
        {
            int ntile = bx >> 3, ks = bx & 7;
            gemm2<2>(h1n, h2o, nullptr, 0,
                     Wih2, 512, 512, Whh2, 512,
                     ntile * 128, 1 << 30, ks * 128, ks * 128 + 128,
                     g_g2p + (long)ks * 131072, 2048, nullptr, nullptr, 0, sh);
            gsync(gs);
        }
        // ---- P4: attention (blocks 0..63, cell2 fused) || logits(t-1) ----
        if (bx < Bsz) {
            int b = bx, lane = tid & 31, w = tid >> 5;
            // cell2 for this batch
            {
                int u = tid;
                float gt[4];
#pragma unroll
                for (int g = 0; g < 4; g++) {
                    int n = g * 512 + u;
                    float s = bih2[n] + bhh2[n];
#pragma unroll
                    for (int ks = 0; ks < 8; ks++)
                        s += g_g2p[ks * 131072 + b * 2048 + n];
                    gt[g] = s;
                }
                float cn = sigf(gt[1]) * g_c2[b * 512 + u] + sigf(gt[0]) * tanhf(gt[2]);
                g_c2[b * 512 + u] = cn;
                float h = sigf(gt[3]) * tanhf(cn);
                h2n[b * 512 + u] = h;
                sh.u.a.h2s[u] = h;
            }
            __syncthreads();
            // q projection (warp per 16 outputs), scale folded
            {
                const float4* h24 = (const float4*)sh.u.a.h2s;
                float4 hv0 = h24[lane], hv1 = h24[32 + lane],
                       hv2 = h24[64 + lane], hv3 = h24[96 + lane];
#pragma unroll 2
                for (int jj = 0; jj < 16; jj++) {
                    int j = w * 16 + jj;
                    const float4* wr = (const float4*)(Wq + (long)j * 512);
                    float4 w0 = wr[lane], w1 = wr[32 + lane],
                           w2 = wr[64 + lane], w3 = wr[96 + lane];
                    float s = hv0.x * w0.x + hv0.y * w0.y + hv0.z * w0.z + hv0.w * w0.w
                            + hv1.x * w1.x + hv1.y * w1.y + hv1.z * w1.z + hv1.w * w1.w
                            + hv2.x * w2.x + hv2.y * w2.y + hv2.z * w2.z + hv2.w * w2.w
                            + hv3.x * w3.x + hv3.y * w3.y + hv3.z * w3.z + hv3.w * w3.w;
#pragma unroll
                    for (int o = 16; o; o >>= 1) s += __shfl_xor_sync(~0u, s, o);
                    if (lane == 0) sh.u.a.qs[j] = (s + bq[j]) * 0.0625f;
                }
            }
            __syncthreads();
            // scores (warp per row, 64 rows/warp)
            {
                const float4* q4 = (const float4*)sh.u.a.qs;
                float4 qr0 = q4[lane], qr1 = q4[32 + lane];
#pragma unroll 2
                for (int i = 0; i < 64; i++) {
                    int sidx = i * 16 + w;
                    const float4* kr = (const float4*)(g_k + ((long)b * 1024 + sidx) * 256);
                    float4 k0 = kr[lane], k1 = kr[32 + lane];
                    float a = qr0.x * k0.x + qr0.y * k0.y + qr0.z * k0.z + qr0.w * k0.w
                            + qr1.x * k1.x + qr1.y * k1.y + qr1.z * k1.z + qr1.w * k1.w;
#pragma unroll
                    for (int o = 16; o; o >>= 1) a += __shfl_xor_sync(~0u, a, o);
                    if (lane == 0) sh.u.a.sc[sidx] = a;
                }
            }
            __syncthreads();
            // softmax
            float inv;
            {
                float* sc = sh.u.a.sc;
                float* red = sh.u.a.red;
                float mx = fmaxf(sc[tid], sc[tid + 512]);
#pragma unroll
                for (int o = 16; o; o >>= 1) mx = fmaxf(mx, __shfl_xor_sync(~0u, mx, o));
                if (lane == 0) red[w] = mx;
                __syncthreads();
                mx = red[0];
#pragma unroll
                for (int i = 1; i < 16; i++) mx = fmaxf(mx, red[i]);
                __syncthreads();
                float e0 = __expf(sc[tid] - mx);
                float e1 = __expf(sc[tid + 512] - mx);
                sc[tid] = e0; sc[tid + 512] = e1;
                float ls = e0 + e1;
#pragma unroll
                for (int o = 16; o; o >>= 1) ls += __shfl_xor_sync(~0u, ls, o);
                if (lane == 0) red[w] = ls;
                __syncthreads();
                float tot = 0.f;
#pragma unroll
                for (int i = 0; i < 16; i++) tot += red[i];
                inv = 1.f / tot;
            }
            // context: thread per column
            {
                const float* sc = sh.u.a.sc;
                const float* vp = g_v + (long)b * (Ssz * Hsz) + tid;
                float a0 = 0.f, a1 = 0.f, a2 = 0.f, a3 = 0.f;
                float a4 = 0.f, a5 = 0.f, a6 = 0.f, a7 = 0.f;
                for (int s2 = 0; s2 < 1024; s2 += 8) {
                    a0 += sc[s2]     * vp[(long)(s2)     * 512];
                    a1 += sc[s2 + 1] * vp[(long)(s2 + 1) * 512];
                    a2 += sc[s2 + 2] * vp[(long)(s2 + 2) * 512];
                    a3 += sc[s2 + 3] * vp[(long)(s2 + 3) * 512];
                    a4 += sc[s2 + 4] * vp[(long)(s2 + 4) * 512];
                    a5 += sc[s2 + 5] * vp[(long)(s2 + 5) * 512];
                    a6 += sc[s2 + 6] * vp[(long)(s2 + 6) * 512];
                    a7 += sc[s2 + 7] * vp[(long)(s2 + 7) * 512];
                }
                g_ctx[b * 512 + tid] =
                    (((a0 + a1) + (a2 + a3)) + ((a4 + a5) + (a6 + a7))) * inv;
            }
            gsync(gs);
        } else {
            // logits(t-1): tiles 0..23 splitK2 -> partials, tiles 24..39 direct
            if (t > 0) {
                int u = bx - 64;
                if (u < 48) {
                    int tile = u >> 1, ks = u & 1;
                    gemm2<0>(g_cdn, nullptr, nullptr, 512,
                             emb, 512, 1 << 30, nullptr, 0,
                             tile * 128, 1 << 30, ks * 256, ks * 256 + 256,
                             g_lgp[ks], 3072, nullptr, nullptr, 0, sh);
                } else {
                    int tile = 24 + (u - 48);
                    gemm2<0>(g_cdn, nullptr, nullptr, 512,
                             emb, 512, 1 << 30, nullptr, 0,
                             tile * 128, Vsz, 0, 512,
                             out + (long)(t - 1) * Vsz, (long)Tsz * Vsz, bcls,
                             nullptr, 0, sh);
                }
            }
            gsync(gs);
        }
        // ---- P5: cdn GEMM (4 n-tiles x splitK32, kchunk 32) ----
        {
            int ntile = bx >> 5, ks = bx & 31;
            gemm2<2>(h2n, g_ctx, nullptr, 0,
                     Wcdn, 1024, 1 << 30, nullptr, 0,
                     ntile * 128, 1 << 30, ks * 32, ks * 32 + 32,
                     g_cdp + (long)ks * 32768, 512, nullptr, nullptr, 0, sh);
            gsync(gs);
        }
        // ---- P6: cdn reduce + logits(t-1) reduce ----
        {
            int gid = bx * NTHR + tid;
            if (gid < 32768) {
                float s = bcdn[gid & 511];
#pragma unroll
                for (int ks = 0; ks < 32; ks++) s += g_cdp[ks * 32768 + gid];
                g_cdn[gid] = fmaxf(s, 0.f);
            }
            if (t > 0) {
#pragma unroll
                for (int rr = 0; rr < 3; rr++) {
                    int e = rr * (GRID * NTHR) + gid;
                    int m = e / 3072, n = e - m * 3072;
                    out[((long)m * Tsz + (t - 1)) * Vsz + n] =
                        g_lgp[0][m * 3072 + n] + g_lgp[1][m * 3072 + n] + bcls[n];
                }
            }
            gsync(gs);
        }
    }
    // ---- final logits for t = Tsz-1 ----
    if (bx < 40) {
        gemm2<0>(g_cdn, nullptr, nullptr, 512,
                 emb, 512, 1 << 30, nullptr, 0,
                 bx * 128, Vsz, 0, 512,
                 out + (long)(Tsz - 1) * Vsz, (long)Tsz * Vsz, bcls,
                 nullptr, 0, sh);
    }
}

extern "C" void kernel_launch(void* const* d_in, const int* in_sizes, int n_in,
                              void* d_out, int out_size) {
    mega<<<GRID, NTHR>>>(
        (const float*)d_in[0],  (const int*)d_in[1],   (const float*)d_in[2],
        (const float*)d_in[3],  (const float*)d_in[4],
        (const float*)d_in[5],  (const float*)d_in[6],
        (const float*)d_in[7],  (const float*)d_in[8],
        (const float*)d_in[9],  (const float*)d_in[10],
        (const float*)d_in[11], (const float*)d_in[12],
        (const float*)d_in[13], (const float*)d_in[14],
        (const float*)d_in[15], (const float*)d_in[16],
        (const float*)d_in[17], (const float*)d_in[18],
        (const float*)d_in[19], (float*)d_out);
}